// round 5
// baseline (speedup 1.0000x reference)
#include <cuda_runtime.h>
#include <cstdint>

#define TT 2048
#define BB 512
#define KK 8
#define DD 32
#define DT_F 0.05f
#define SQDT_F 0.22360679774997896f  /* sqrt(0.05) */
#define UN 4                          /* prefetch group / unroll */

// Scratch: normalized weights wn[t][b][k] = s_probs / sum_k. Static (no allocs).
__device__ float g_wn[TT * BB * KK];

// ---------- f32x2 helpers (FFMA2 is PTX-only on sm_103a) ----------
__device__ __forceinline__ unsigned long long add2(unsigned long long a, unsigned long long b) {
    unsigned long long d;
    asm("add.rn.f32x2 %0, %1, %2;" : "=l"(d) : "l"(a), "l"(b));
    return d;
}
__device__ __forceinline__ void ffma2(unsigned long long& d, unsigned long long a, unsigned long long b) {
    asm("fma.rn.f32x2 %0, %1, %2, %3;" : "=l"(d) : "l"(a), "l"(b), "l"(d));
}
__device__ __forceinline__ float hsum2(unsigned long long v) {
    float lo, hi;
    asm("mov.b64 {%0, %1}, %2;" : "=f"(lo), "=f"(hi) : "l"(v));
    return lo + hi;
}

// ---------- Kernel 1: normalized weights ----------
__global__ void __launch_bounds__(256) norm_kernel(const float* __restrict__ s_probs) {
    int idx = blockIdx.x * blockDim.x + threadIdx.x;  // (t,b) pair
    if (idx < TT * BB) {
        const float4* p = (const float4*)(s_probs + (size_t)idx * KK);
        float4 a = p[0];
        float4 b = p[1];
        float s = ((a.x + a.y) + (a.z + a.w)) + ((b.x + b.y) + (b.z + b.w));
        float r = 1.0f / s;
        float4* o = (float4*)(g_wn + (size_t)idx * KK);
        o[0] = make_float4(a.x * r, a.y * r, a.z * r, a.w * r);
        o[1] = make_float4(b.x * r, b.y * r, b.z * r, b.w * r);
    }
}

// ---------- Kernel 2: one CTA (128 thr = 4 warps) per TWO batches ----------
// Warp w: pair = w>>1 (which batch), wp = w&1 (which k-half, kb = 4*wp).
// Lane i of the warp owns row i of A_{kb..kb+3} in registers (128 regs).
// k-reduction over the warp's 4 k's is register math; cross-warp reduction is
// one float2 smem exchange with the partner warp. 4 warps cover 4 SMSPs.
__global__ void __launch_bounds__(128, 2) sde_main(
    const float* __restrict__ z0,
    const float* __restrict__ noise,
    const float* __restrict__ A_s,
    const float* __restrict__ b_s,
    const float* __restrict__ Q_chol,
    float* __restrict__ ys)
{
    const int tid  = threadIdx.x;
    const int w    = tid >> 5;       // 0..3
    const int lane = tid & 31;       // row i
    const int pair = w >> 1;         // batch-within-CTA
    const int wp   = w & 1;          // warp-within-pair
    const int kb   = wp * 4;         // k base
    const int b    = blockIdx.x * 2 + pair;

    __shared__ __align__(16) float  zbuf[2][2][DD];     // [pair][wp][row] private z
    __shared__ __align__(16) float2 pbuf[2][2][2][DD];  // [parity][pair][wp][row]

    // ---- A rows -> registers as f32x2 pairs: A[kk] = row `lane` of A_{kb+kk} ----
    unsigned long long A[4][16];
#pragma unroll
    for (int kk = 0; kk < 4; kk++) {
        const ulonglong2* r = (const ulonglong2*)(A_s + (size_t)((kb + kk) * DD + lane) * DD);
#pragma unroll
        for (int q = 0; q < 8; q++) {
            ulonglong2 v = r[q];
            A[kk][2 * q]     = v.x;
            A[kk][2 * q + 1] = v.y;
        }
    }
    float dtb[4], qc[4];
#pragma unroll
    for (int kk = 0; kk < 4; kk++) {
        dtb[kk] = DT_F * b_s[(kb + kk) * DD + lane];
        qc[kk]  = Q_chol[(kb + kk) * DD + lane];
    }

    // ---- z init ----
    float zreg = z0[(size_t)b * DD + lane];
    zbuf[pair][wp][lane] = zreg;

    // stream pointers
    const float4* wp4 = (const float4*)g_wn;            // idx = ((t*BB+b)*KK)/4 + wp
    const float*  np  = noise + (size_t)b * DD + lane;  // + step*BB*DD
    float*        yp  = ys    + (size_t)b * DD + lane;

    // ---- prefetch group 0 ----
    float4 w4_c[UN]; float dw_c[UN];
#pragma unroll
    for (int u = 0; u < UN; u++) {
        w4_c[u] = __ldg(&wp4[((size_t)u * BB + b) * 2 + wp]);
        dw_c[u] = SQDT_F * __ldg(&np[(size_t)u * (BB * DD)]);
    }

    __syncthreads();

    for (int s0 = 0; s0 < TT; s0 += UN) {
        // ---- prefetch next group (clamped; last-group values unused) ----
        float4 w4_n[UN]; float dw_n[UN];
#pragma unroll
        for (int u = 0; u < UN; u++) {
            int ts = s0 + UN + u;
            if (ts >= TT) ts = TT - 1;
            w4_n[u] = __ldg(&wp4[((size_t)ts * BB + b) * 2 + wp]);
            dw_n[u] = SQDT_F * __ldg(&np[(size_t)ts * (BB * DD)]);
        }

#pragma unroll
        for (int u = 0; u < UN; u++) {
            const int step = s0 + u;
            const int par  = step & 1;

            // ---- matvec: 4 rows (one per k) against z (8 LDS.128 + 64 FFMA2) ----
            unsigned long long ca[4] = {0ull, 0ull, 0ull, 0ull};
            unsigned long long cb[4] = {0ull, 0ull, 0ull, 0ull};
            const ulonglong2* zv = (const ulonglong2*)(&zbuf[pair][wp][0]);
#pragma unroll
            for (int jj = 0; jj < 8; jj++) {
                ulonglong2 z2 = zv[jj];                 // LDS.128 broadcast
#pragma unroll
                for (int kk = 0; kk < 4; kk++) {
                    ffma2(ca[kk], A[kk][2 * jj],     z2.x);
                    ffma2(cb[kk], A[kk][2 * jj + 1], z2.y);
                }
            }
            float a0 = hsum2(add2(ca[0], cb[0]));
            float a1 = hsum2(add2(ca[1], cb[1]));
            float a2 = hsum2(add2(ca[2], cb[2]));
            float a3 = hsum2(add2(ca[3], cb[3]));

            // ---- weighted combine over this warp's 4 k's (register math) ----
            float4 wv = w4_c[u];
            float pd = fmaf(wv.x, fmaf(DT_F, a0, dtb[0]),
                       fmaf(wv.y, fmaf(DT_F, a1, dtb[1]),
                       fmaf(wv.z, fmaf(DT_F, a2, dtb[2]),
                            wv.w * fmaf(DT_F, a3, dtb[3]))));
            float pq = fmaf(wv.x, qc[0],
                       fmaf(wv.y, qc[1],
                       fmaf(wv.z, qc[2], wv.w * qc[3])));

            // ---- cross-warp reduction: one smem exchange + one barrier ----
            pbuf[par][pair][wp][lane] = make_float2(pd, pq);
            __syncthreads();
            float2 o = pbuf[par][pair][wp ^ 1][lane];
            pd += o.x;
            pq += o.y;

            // ---- z update (both warps of the pair redundantly) ----
            zreg = fmaf(pq, dw_c[u], zreg + pd);
            zbuf[pair][wp][lane] = zreg;
            if (wp == 0) yp[(size_t)step * (BB * DD)] = zreg;  // coalesced 128B
            __syncwarp();
        }

        // rotate prefetch buffers
#pragma unroll
        for (int u = 0; u < UN; u++) {
            w4_c[u] = w4_n[u];
            dw_c[u] = dw_n[u];
        }
    }
}

extern "C" void kernel_launch(void* const* d_in, const int* in_sizes, int n_in,
                              void* d_out, int out_size) {
    const float* z0      = (const float*)d_in[0];
    const float* s_probs = (const float*)d_in[1];
    const float* noise   = (const float*)d_in[2];
    const float* A_s     = (const float*)d_in[3];
    const float* b_s     = (const float*)d_in[4];
    const float* Q_chol  = (const float*)d_in[5];
    float*       ys      = (float*)d_out;

    norm_kernel<<<(TT * BB + 255) / 256, 256>>>(s_probs);
    sde_main<<<BB / 2, 128>>>(z0, noise, A_s, b_s, Q_chol, ys);
}